// round 17
// baseline (speedup 1.0000x reference)
#include <cuda_runtime.h>
#include <cuda_fp16.h>
#include <cstdint>

#define BATCH 64
#define HDIM 512
#define HH 262144      // HDIM*HDIM
#define NSEQ 2048
#define NFOCUS 256

// ---------------- scratch (static device globals; no runtime allocation) ----
__device__ float g_Y[(size_t)BATCH * HH];      // 64 MB (Yq only; Yk never stored)
__device__ float g_Qp[8 * BATCH * HDIM];
__device__ float g_Q[BATCH * HDIM];
__device__ float g_wp[4 * BATCH * HDIM];       // per-k-quarter w partials
__device__ float g_w[BATCH * HDIM];
__device__ float g_compat[BATCH * NSEQ];

// ======================= mma.sync helpers (HMMA path) =======================
__device__ __forceinline__ uint32_t smem_u32(const void* p) {
    uint32_t a;
    asm("{ .reg .u64 t; cvta.to.shared.u64 t, %1; cvt.u32.u64 %0, t; }"
        : "=r"(a) : "l"(p));
    return a;
}
__device__ __forceinline__ void ldsm4(uint32_t* r, uint32_t a) {
    asm volatile("ldmatrix.sync.aligned.m8n8.x4.shared.b16 {%0,%1,%2,%3}, [%4];"
                 : "=r"(r[0]), "=r"(r[1]), "=r"(r[2]), "=r"(r[3]) : "r"(a));
}
__device__ __forceinline__ void mma16816(float* c, const uint32_t* a, const uint32_t* b) {
    asm volatile(
        "mma.sync.aligned.m16n8k16.row.col.f32.f16.f16.f32 "
        "{%0,%1,%2,%3}, {%4,%5,%6,%7}, {%8,%9}, {%0,%1,%2,%3};"
        : "+f"(c[0]), "+f"(c[1]), "+f"(c[2]), "+f"(c[3])
        : "r"(a[0]), "r"(a[1]), "r"(a[2]), "r"(a[3]), "r"(b[0]), "r"(b[1]));
}
// Split a PAIR of fp32 into two packed fp16 levels with only 2 cvt instrs.
__device__ __forceinline__ void split_pair(float x0, float x1,
                                           uint32_t& uA, uint32_t& uB) {
    uint32_t b0 = __float_as_uint(x0), b1 = __float_as_uint(x1);
    float t0 = __uint_as_float((b0 + 0xFFFu + ((b0 >> 13) & 1u)) & 0xFFFFE000u);
    float t1 = __uint_as_float((b1 + 0xFFFu + ((b1 >> 13) & 1u)) & 0xFFFFE000u);
    float r0 = (x0 - t0) * 2048.0f;
    float r1 = (x1 - t1) * 2048.0f;
    asm("cvt.rn.f16x2.f32 %0, %1, %2;" : "=r"(uA) : "f"(t1), "f"(t0));
    asm("cvt.rn.f16x2.f32 %0, %1, %2;" : "=r"(uB) : "f"(r1), "f"(r0));
}

// ========= emulated-fp32 GEMM via 2-way fp16 split (3 HMMA products) ========
// 2 CTAs/SM, proven round-15 mainloop. MODE=0: epilogue stores Y (stage 1).
// MODE=1: epilogue fuses contract_w: dot accumulators with Q (smem tile),
// deterministic reduce, write g_wp[k-quarter][b][h0]; Y never stored.
#define KC 32                        // k per chunk
#define NCHUNK (HDIM / KC)           // 16
#define NTILE 128                    // n per CTA
#define THREADS 256
#define ROWB 80                      // padded fp16 smem row bytes (64B + 16 pad)
#define WS_OFF(buf, lvl)  ((buf) * 30720u + (lvl) * 10240u)           // 128n x 32k
#define XS_OFF(buf, lvl)  ((buf) * 30720u + 20480u + (lvl) * 5120u)   // 64b x 32k
#define SMEM_BYTES 61440

template <int MODE>
__global__ __launch_bounds__(THREADS, 2) void gemm_mma(
    const float* __restrict__ X, const float* __restrict__ W,
    const float* __restrict__ bias)
{
    extern __shared__ __align__(16) char smem_raw[];
    const uint32_t sb = smem_u32(smem_raw);
    const int tid = threadIdx.x;
    const int wid = tid >> 5, lane = tid & 31;
    const int n0 = blockIdx.x * NTILE;

    const int mpair = wid & 1;
    const int noct  = wid >> 1;

    float lo[2][4][4], hi[2][4][4];
    #pragma unroll
    for (int m = 0; m < 2; m++)
        #pragma unroll
        for (int j = 0; j < 4; j++)
            #pragma unroll
            for (int q = 0; q < 4; q++) { lo[m][j][q] = 0.f; hi[m][j][q] = 0.f; }

    const int wn = tid & 127, wkh = tid >> 7;
    const int xb = tid >> 2, xq = tid & 3;

    float  wr[16];
    float4 xr0, xr1;

    const uint32_t a_row  = (uint32_t)(32 * mpair + (lane & 15)) * ROWB + ((lane >> 4) << 4);
    const uint32_t b_row4 = (uint32_t)(noct * 32 + (lane & 7) + ((lane >> 4) << 3)) * ROWB
                          + (((lane >> 3) & 1) << 4);

    #define WLOAD(chunk) do {                                                    \
        const float* wsrc = W + (size_t)((chunk) * KC + wkh * 16) * HH + n0 + wn;\
        _Pragma("unroll")                                                        \
        for (int j = 0; j < 16; j++)                                             \
            wr[j] = __ldcs(wsrc + (size_t)j * HH);                               \
    } while (0)

    #define XLOAD(chunk) do {                                                    \
        const float* xsrc = X + (size_t)xb * HDIM + (chunk) * KC + xq * 8;       \
        xr0 = __ldg((const float4*)xsrc);                                        \
        xr1 = __ldg((const float4*)(xsrc + 4));                                  \
    } while (0)

    #define CONVERT_STAGE(buf) do {                                              \
        uint32_t u1[8], u2[8];                                                   \
        _Pragma("unroll")                                                        \
        for (int p = 0; p < 8; p++)                                              \
            split_pair(wr[2 * p], wr[2 * p + 1], u1[p], u2[p]);                  \
        const uint32_t rb = (uint32_t)wn * ROWB + wkh * 32;                      \
        asm volatile("st.shared.v4.b32 [%0], {%1,%2,%3,%4};" ::                  \
            "r"(sb + WS_OFF(buf, 0) + rb), "r"(u1[0]), "r"(u1[1]), "r"(u1[2]), "r"(u1[3]) : "memory"); \
        asm volatile("st.shared.v4.b32 [%0], {%1,%2,%3,%4};" ::                  \
            "r"(sb + WS_OFF(buf, 0) + rb + 16), "r"(u1[4]), "r"(u1[5]), "r"(u1[6]), "r"(u1[7]) : "memory"); \
        asm volatile("st.shared.v4.b32 [%0], {%1,%2,%3,%4};" ::                  \
            "r"(sb + WS_OFF(buf, 1) + rb), "r"(u2[0]), "r"(u2[1]), "r"(u2[2]), "r"(u2[3]) : "memory"); \
        asm volatile("st.shared.v4.b32 [%0], {%1,%2,%3,%4};" ::                  \
            "r"(sb + WS_OFF(buf, 1) + rb + 16), "r"(u2[4]), "r"(u2[5]), "r"(u2[6]), "r"(u2[7]) : "memory"); \
        uint32_t v1[4], v2[4];                                                   \
        split_pair(xr0.x, xr0.y, v1[0], v2[0]);                                  \
        split_pair(xr0.z, xr0.w, v1[1], v2[1]);                                  \
        split_pair(xr1.x, xr1.y, v1[2], v2[2]);                                  \
        split_pair(xr1.z, xr1.w, v1[3], v2[3]);                                  \
        const uint32_t xrb = (uint32_t)xb * ROWB + xq * 16;                      \
        asm volatile("st.shared.v4.b32 [%0], {%1,%2,%3,%4};" ::                  \
            "r"(sb + XS_OFF(buf, 0) + xrb), "r"(v1[0]), "r"(v1[1]), "r"(v1[2]), "r"(v1[3]) : "memory"); \
        asm volatile("st.shared.v4.b32 [%0], {%1,%2,%3,%4};" ::                  \
            "r"(sb + XS_OFF(buf, 1) + xrb), "r"(v2[0]), "r"(v2[1]), "r"(v2[2]), "r"(v2[3]) : "memory"); \
    } while (0)

    WLOAD(0); XLOAD(0);
    CONVERT_STAGE(0);
    WLOAD(1); XLOAD(1);

    for (int kc = 0; kc < NCHUNK; kc++) {
        __syncthreads();

        if (kc + 1 < NCHUNK) {
            CONVERT_STAGE((kc + 1) & 1);
            if (kc + 2 < NCHUNK) { WLOAD(kc + 2); XLOAD(kc + 2); }
        }

        const int cur = kc & 1;
        #pragma unroll
        for (int ks = 0; ks < 2; ks++) {
            uint32_t a1[2][4], a2[2][4];
            #pragma unroll
            for (int m = 0; m < 2; m++) {
                ldsm4(a1[m], sb + XS_OFF(cur, 0) + a_row + (uint32_t)m * (16 * ROWB) + ks * 32);
                ldsm4(a2[m], sb + XS_OFF(cur, 1) + a_row + (uint32_t)m * (16 * ROWB) + ks * 32);
            }
            #pragma unroll
            for (int jp = 0; jp < 4; jp += 2) {
                uint32_t B1[4], B2[4];
                ldsm4(B1, sb + WS_OFF(cur, 0) + b_row4 + (uint32_t)jp * (8 * ROWB) + ks * 32);
                ldsm4(B2, sb + WS_OFF(cur, 1) + b_row4 + (uint32_t)jp * (8 * ROWB) + ks * 32);
                #pragma unroll
                for (int m = 0; m < 2; m++) {
                    mma16816(lo[m][jp],     a1[m], &B1[0]);
                    mma16816(lo[m][jp + 1], a1[m], &B1[2]);
                    mma16816(hi[m][jp],     a1[m], &B2[0]);
                    mma16816(hi[m][jp + 1], a1[m], &B2[2]);
                    mma16816(hi[m][jp],     a2[m], &B1[0]);
                    mma16816(hi[m][jp + 1], a2[m], &B1[2]);
                }
            }
        }
    }

    const float s = 1.0f / 2048.0f;
    if (MODE == 0) {
        // ---- epilogue: Y = lo + hi/2048 + bias -> g_Y ----
        const int ncol = n0 + noct * 32 + (lane & 3) * 2;
        #pragma unroll
        for (int m = 0; m < 2; m++) {
            const int brow = 32 * mpair + 16 * m + (lane >> 2);
            #pragma unroll
            for (int j = 0; j < 4; j++) {
                const int n = ncol + j * 8;
                const float2 bz = *(const float2*)&bias[n];
                float2 o0 = make_float2(fmaf(hi[m][j][0], s, lo[m][j][0]) + bz.x,
                                        fmaf(hi[m][j][1], s, lo[m][j][1]) + bz.y);
                float2 o1 = make_float2(fmaf(hi[m][j][2], s, lo[m][j][2]) + bz.x,
                                        fmaf(hi[m][j][3], s, lo[m][j][3]) + bz.y);
                *(float2*)&g_Y[(size_t)brow * HH + n]       = o0;
                *(float2*)&g_Y[(size_t)(brow + 8) * HH + n] = o1;
            }
        }
    } else {
        // ---- epilogue: fused contract_w partial: wp[b, h0] += <Y_tile, Q> ----
        __syncthreads();   // fp16 buffers dead; reuse smem
        float* qs   = (float*)smem_raw;                      // [64][132]
        float* wred = (float*)(smem_raw + 64 * 132 * 4);     // [64][4]
        const int kbase = n0 & 511;
        const int h0 = n0 >> 9;
        const int q4 = (n0 >> 7) & 3;
        #pragma unroll
        for (int it = 0; it < 32; it++) {
            const int e = tid + it * 256;
            const int b = e >> 7, kl = e & 127;
            qs[b * 132 + kl] = g_Q[(b << 9) + kbase + kl];
        }
        __syncthreads();
        const int klb = noct * 32 + (lane & 3) * 2;
        const int r0  = 32 * mpair + (lane >> 2);
        float ws4[4] = {0.f, 0.f, 0.f, 0.f};
        #pragma unroll
        for (int m = 0; m < 2; m++) {
            #pragma unroll
            for (int j = 0; j < 4; j++) {
                const int kl = klb + j * 8;
                const float2 bz = *(const float2*)&bias[n0 + kl];
                const float y00 = fmaf(hi[m][j][0], s, lo[m][j][0]) + bz.x;
                const float y01 = fmaf(hi[m][j][1], s, lo[m][j][1]) + bz.y;
                const float y10 = fmaf(hi[m][j][2], s, lo[m][j][2]) + bz.x;
                const float y11 = fmaf(hi[m][j][3], s, lo[m][j][3]) + bz.y;
                const int ra = r0 + 16 * m, rb2 = ra + 8;
                ws4[2 * m]     += y00 * qs[ra * 132 + kl]  + y01 * qs[ra * 132 + kl + 1];
                ws4[2 * m + 1] += y10 * qs[rb2 * 132 + kl] + y11 * qs[rb2 * 132 + kl + 1];
            }
        }
        #pragma unroll
        for (int off = 1; off <= 2; off <<= 1)
            #pragma unroll
            for (int i = 0; i < 4; i++)
                ws4[i] += __shfl_xor_sync(~0u, ws4[i], off);
        if ((lane & 3) == 0) {
            wred[(r0 +  0) * 4 + noct] = ws4[0];
            wred[(r0 +  8) * 4 + noct] = ws4[1];
            wred[(r0 + 16) * 4 + noct] = ws4[2];
            wred[(r0 + 24) * 4 + noct] = ws4[3];
        }
        __syncthreads();
        if (tid < 64) {
            const float v = ((wred[tid * 4 + 0] + wred[tid * 4 + 1])
                           + wred[tid * 4 + 2]) + wred[tid * 4 + 3];
            g_wp[((q4 << 6) + tid) * 512 + h0] = v;
        }
    }
    #undef WLOAD
    #undef XLOAD
    #undef CONVERT_STAGE
}

// ---------------- Qpart[s,b,k] = sum_{h in slice s} x[b,h] * Y[b, h*H + k] --
__global__ void contract_q(const float* __restrict__ X) {
    const int b = blockIdx.y, s = blockIdx.x;
    const int k = threadIdx.x;  // 512
    __shared__ float xs[64];
    if (k < 64) xs[k] = X[b * HDIM + s * 64 + k];
    __syncthreads();
    const float* Yb = g_Y + (size_t)b * HH + (size_t)s * 64 * HDIM + k;
    float a0 = 0.f, a1 = 0.f, a2 = 0.f, a3 = 0.f;
    #pragma unroll
    for (int hh = 0; hh < 64; hh += 4) {
        a0 = fmaf(xs[hh + 0], __ldcs(&Yb[(hh + 0) * HDIM]), a0);
        a1 = fmaf(xs[hh + 1], __ldcs(&Yb[(hh + 1) * HDIM]), a1);
        a2 = fmaf(xs[hh + 2], __ldcs(&Yb[(hh + 2) * HDIM]), a2);
        a3 = fmaf(xs[hh + 3], __ldcs(&Yb[(hh + 3) * HDIM]), a3);
    }
    g_Qp[(s * BATCH + b) * HDIM + k] = (a0 + a1) + (a2 + a3);
}

__global__ void reduce_q() {
    const int b = blockIdx.x, k = threadIdx.x;
    float v = 0.f;
    #pragma unroll
    for (int s = 0; s < 8; s++) v += g_Qp[(s * BATCH + b) * HDIM + k];
    g_Q[b * HDIM + k] = v;
}

// ---------------- w[b,h] = sum of 4 k-quarter partials (fixed order) --------
__global__ void reduce_w() {
    const int b = blockIdx.x, h = threadIdx.x;
    const float v = ((g_wp[(b) * 512 + h] + g_wp[(64 + b) * 512 + h])
                   + g_wp[(128 + b) * 512 + h]) + g_wp[(192 + b) * 512 + h];
    g_w[b * HDIM + h] = v;
}

// ---------------- compat[b,n] = norm * < ve[b,n,:], w[b,:] > ----------------
__global__ void compat_k(const float* __restrict__ ve) {
    const int b = blockIdx.y;
    const int warp = threadIdx.x >> 5, lane = threadIdx.x & 31;
    const int n = blockIdx.x * 16 + warp * 2;
    __shared__ float ws[HDIM];
    for (int i = threadIdx.x; i < HDIM; i += 256) ws[i] = g_w[b * HDIM + i];
    __syncthreads();
    const float* v0 = ve + ((size_t)b * NSEQ + n) * HDIM;
    const float* v1 = v0 + HDIM;
    float acc0 = 0.f, acc1 = 0.f;
    #pragma unroll
    for (int s2 = 0; s2 < 4; s2++) {
        const int i4 = (lane + s2 * 32) * 4;
        float4 q  = *(const float4*)&ws[i4];
        float4 y0 = __ldcs((const float4*)&v0[i4]);
        float4 y1 = __ldcs((const float4*)&v1[i4]);
        acc0 += y0.x * q.x + y0.y * q.y + y0.z * q.z + y0.w * q.w;
        acc1 += y1.x * q.x + y1.y * q.y + y1.z * q.z + y1.w * q.w;
    }
    #pragma unroll
    for (int off = 16; off; off >>= 1) {
        acc0 += __shfl_xor_sync(~0u, acc0, off);
        acc1 += __shfl_xor_sync(~0u, acc1, off);
    }
    if (lane == 0) {
        g_compat[b * NSEQ + n]     = acc0 * 0.04419417382415922f;
        g_compat[b * NSEQ + n + 1] = acc1 * 0.04419417382415922f;
    }
}

// ------- per-batch ranking (fp32-exp flush boundary) + fused gather ---------
__global__ __launch_bounds__(1024) void topk_gather(
    const float* __restrict__ ve, float* __restrict__ out)
{
    __shared__ unsigned sk[NSEQ];
    __shared__ int      si[NSEQ];
    __shared__ float    redf[32];
    const int b = blockIdx.x, t = threadIdx.x;
    const int lane = t & 31, warp = t >> 5;

    const float c0 = g_compat[b * NSEQ + t];
    const float c1 = g_compat[b * NSEQ + t + 1024];

    float m = fmaxf(c0, c1);
    #pragma unroll
    for (int o = 16; o; o >>= 1) m = fmaxf(m, __shfl_xor_sync(~0u, m, o));
    if (lane == 0) redf[warp] = m;
    __syncthreads();
    float mx = redf[0];
    #pragma unroll
    for (int i = 1; i < 32; i++) mx = fmaxf(mx, redf[i]);

    auto mkkey = [&](float c) -> unsigned {
        float d = c - mx;
        if (d < -87.33654785f) return 0u;
        unsigned u = __float_as_uint(c);
        return (u & 0x80000000u) ? ~u : (u | 0x80000000u);
    };
    sk[t]        = mkkey(c0);  si[t]        = t;
    sk[t + 1024] = mkkey(c1);  si[t + 1024] = t + 1024;

    for (int k = 2; k <= NSEQ; k <<= 1) {
        for (int j = k >> 1; j > 0; j >>= 1) {
            __syncthreads();
            #pragma unroll
            for (int half = 0; half < 2; half++) {
                const int i = half * 1024 + t;
                const int ixj = i ^ j;
                if (ixj > i) {
                    const bool desc = ((i & k) == 0);
                    unsigned ki = sk[i], kj = sk[ixj];
                    int      ii = si[i], ij = si[ixj];
                    const bool jBeforeI = (kj > ki) || (kj == ki && ij < ii);
                    if (desc ? jBeforeI : !jBeforeI) {
                        sk[i] = kj; sk[ixj] = ki;
                        si[i] = ij; si[ixj] = ii;
                    }
                }
            }
        }
    }
    __syncthreads();

    // fused gather: out[b,r,:] = ve[b, si[r], :]
    const float4* vesrc = (const float4*)(ve + (size_t)b * NSEQ * HDIM);
    float4* dst = (float4*)(out + (size_t)b * NFOCUS * HDIM);
    const int r = t >> 2, seg = t & 3;          // 256 rows x 4 segments
    const int idx = si[r];
    #pragma unroll
    for (int i = 0; i < 32; i++)
        dst[r * 128 + seg * 32 + i] = vesrc[(size_t)idx * 128 + seg * 32 + i];
}

// ---------------- launch ----------------------------------------------------
extern "C" void kernel_launch(void* const* d_in, const int* in_sizes, int n_in,
                              void* d_out, int out_size) {
    const float* vs = (const float*)d_in[0];   // (64, 1, 512)
    const float* ve = (const float*)d_in[1];   // (64, 2048, 512)
    const float* Wq = (const float*)d_in[2];   // (512, 262144)
    const float* bq = (const float*)d_in[3];   // (262144,)
    const float* Wk = (const float*)d_in[4];   // (512, 262144)
    const float* bk = (const float*)d_in[5];   // (262144,)
    float* out = (float*)d_out;                // (64, 256, 512)

    cudaFuncSetAttribute(gemm_mma<0>, cudaFuncAttributeMaxDynamicSharedMemorySize, SMEM_BYTES);
    cudaFuncSetAttribute(gemm_mma<1>, cudaFuncAttributeMaxDynamicSharedMemorySize, SMEM_BYTES);

    // Stage 1: Yq -> g_Y ; Q = contract(x, Yq)
    gemm_mma<0><<<HH / NTILE, THREADS, SMEM_BYTES>>>(vs, Wq, bq);
    contract_q<<<dim3(8, BATCH), 512>>>(vs);
    reduce_q<<<BATCH, HDIM>>>();

    // Stage 2: fused — w partials computed in gemm epilogue (Yk never stored)
    gemm_mma<1><<<HH / NTILE, THREADS, SMEM_BYTES>>>(vs, Wk, bk);
    reduce_w<<<BATCH, HDIM>>>();

    // Stage 3: compat -> softmax-faithful ranking + gather
    compat_k<<<dim3(NSEQ / 16, BATCH), 256>>>(ve);
    topk_gather<<<BATCH, 1024>>>(ve, out);
}